// round 13
// baseline (speedup 1.0000x reference)
#include <cuda_runtime.h>
#include <cuda_bf16.h>
#include <cstdint>

// Problem constants
#define MDIM 16384
#define NDIM 16384
#define KDIM 512
#define ALPHA_C 0.1f
#define NU_C 1e-3f

#define MT 128
#define NT 128
#define NTILES (NDIM / NT)          // 128

// smem layout (bytes)
#define SM_A   0                    // 4 chunks x [128 x 128B] SW128 = 65536
#define SM_B   65536                // 4-slot ring x 16384 = 65536
#define SM_M2  131072               // m2: 2x128 floats, sm: 2x128 floats = 2048
#define SM_STG 133120               // 128 x 24 floats = 12288
#define SMEM_BYTES 145408

// Scratch
__device__ __align__(16) float  g_Af[MDIM * KDIM];   // transposed phi fp32
__device__ __align__(16) int8_t g_A8[MDIM * KDIM];
__device__ __align__(16) int8_t g_B8[NDIM * KDIM];
__device__ float g_x2[MDIM];
__device__ float g_m2[NDIM];
__device__ float g_sx[MDIM];
__device__ float g_sm[NDIM];
__device__ float g_part[MDIM / MT];

// ---------------- PTX helpers ----------------
#define CP16(dst, src) \
  asm volatile("cp.async.cg.shared.global [%0], [%1], 16;\n" :: "r"(dst), "l"(src))
#define CP_COMMIT() asm volatile("cp.async.commit_group;\n" ::: "memory")
#define CP_WAIT(n)  asm volatile("cp.async.wait_group %0;\n" :: "n"(n) : "memory")

#define LDSM4(R0, R1, R2, R3, ADDR) \
  asm volatile("ldmatrix.sync.aligned.m8n8.x4.shared.b16 {%0,%1,%2,%3}, [%4];" \
               : "=r"(R0), "=r"(R1), "=r"(R2), "=r"(R3) : "r"(ADDR))

#define MMA16832_S8(C, A, B0, B1) \
  asm volatile("mma.sync.aligned.m16n8k32.row.col.s32.s8.s8.s32 " \
               "{%0,%1,%2,%3},{%4,%5,%6,%7},{%8,%9},{%0,%1,%2,%3};" \
               : "+r"((C)[0]), "+r"((C)[1]), "+r"((C)[2]), "+r"((C)[3]) \
               : "r"((A)[0]), "r"((A)[1]), "r"((A)[2]), "r"((A)[3]), \
                 "r"(B0), "r"(B1))

#define SWZ128(x) ((x) ^ (((x) >> 3) & 0x70))

// ---------------- Prep kernels ----------------
// transpose phi (4,512,64,64) -> g_Af[(b*4096+hw)][c] fp32
__global__ void prep_phi(const float* __restrict__ phi) {
    __shared__ float t[32][33];
    int b = blockIdx.z, c0 = blockIdx.y * 32, h0 = blockIdx.x * 32;
    int tx = threadIdx.x, ty = threadIdx.y;
    const float* p = phi + ((size_t)b * 512 + c0) * 4096 + h0;
#pragma unroll
    for (int i = 0; i < 4; i++)
        t[ty + 8 * i][tx] = p[(size_t)(ty + 8 * i) * 4096 + tx];
    __syncthreads();
#pragma unroll
    for (int i = 0; i < 4; i++) {
        int row = ty + 8 * i;
        g_Af[((size_t)b * 4096 + h0 + row) * 512 + c0 + tx] = t[tx][row];
    }
}

// quantize one row per warp: sumsq (exact fp32), maxabs, int8 rn quantize
__device__ __forceinline__ void quant_row(const float* __restrict__ src,
                                          int8_t* __restrict__ dst,
                                          float* x2out, float* sout,
                                          int row, int lane) {
    const float4* p = (const float4*)(src + (size_t)row * 512) + lane * 4;
    float v[16];
    float ss = 0.f, mx = 0.f;
#pragma unroll
    for (int i = 0; i < 4; i++) {
        float4 f = p[i];
        v[4 * i] = f.x; v[4 * i + 1] = f.y; v[4 * i + 2] = f.z; v[4 * i + 3] = f.w;
    }
#pragma unroll
    for (int j = 0; j < 16; j++) { ss = fmaf(v[j], v[j], ss); mx = fmaxf(mx, fabsf(v[j])); }
#pragma unroll
    for (int o = 16; o > 0; o >>= 1) {
        ss += __shfl_xor_sync(0xffffffffu, ss, o);
        mx = fmaxf(mx, __shfl_xor_sync(0xffffffffu, mx, o));
    }
    float inv = (mx > 0.f) ? 127.f / mx : 0.f;
    uint32_t w[4];
#pragma unroll
    for (int i = 0; i < 4; i++) {
        uint32_t pk = 0;
#pragma unroll
        for (int j = 0; j < 4; j++) {
            int q = __float2int_rn(v[4 * i + j] * inv);
            pk |= (uint32_t)(q & 0xff) << (8 * j);
        }
        w[i] = pk;
    }
    ((uint4*)(dst + (size_t)row * 512))[lane] = make_uint4(w[0], w[1], w[2], w[3]);
    if (lane == 0) { x2out[row] = ss; sout[row] = (mx > 0.f) ? mx / 127.f : 0.f; }
}

__global__ void prep_xq(void) {
    int row  = (blockIdx.x * 256 + threadIdx.x) >> 5;
    quant_row(g_Af, g_A8, g_x2, g_sx, row, threadIdx.x & 31);
}

__global__ void prep_mq(const float* __restrict__ mem) {
    int row  = (blockIdx.x * 256 + threadIdx.x) >> 5;
    quant_row(mem, g_B8, g_m2, g_sm, row, threadIdx.x & 31);
}

// ---------------- Main fused kernel ----------------
__device__ __forceinline__ void insert6a(float v, float (&q)[6]) {
    if (v < q[5]) {
        q[5] = v;
        if (q[5] < q[4]) { float t = q[4]; q[4] = q[5]; q[5] = t;
            if (q[4] < q[3]) { t = q[3]; q[3] = q[4]; q[4] = t;
                if (q[3] < q[2]) { t = q[2]; q[2] = q[3]; q[3] = t;
                    if (q[2] < q[1]) { t = q[1]; q[1] = q[2]; q[2] = t;
                        if (q[1] < q[0]) { t = q[0]; q[0] = q[1]; q[1] = t; } } } } }
    }
}

// stage sk (k-chunk 0..3, 128 int8) of tile n0 into ring slot
__device__ __forceinline__ void b_stage(uint32_t bOff, int slot, int n0, int sk, int tid) {
#pragma unroll
    for (int i = 0; i < 2; i++) {
        int c = tid + i * 512;                // 1024 16B-units: 128 rows x 8 segs
        int row = c >> 3, seg = c & 7;
        uint32_t dst = bOff + (uint32_t)(slot * 16384 + SWZ128(row * 128 + seg * 16));
        CP16(dst, g_B8 + (size_t)(n0 + row) * 512 + sk * 128 + seg * 16);
    }
}

__global__ __launch_bounds__(512, 1)
void knn_gemm(const float* __restrict__ rptr) {
    extern __shared__ char smem[];
    float* m2s   = (float*)(smem + SM_M2);          // [2][128]
    float* sms   = (float*)(smem + SM_M2 + 1024);   // [2][128]
    float* stage = (float*)(smem + SM_STG);

    const int tid  = threadIdx.x;
    const int lane = tid & 31;
    const int warp = tid >> 5;
    const int wm   = warp & 3;
    const int wn   = warp >> 2;
    const int m0   = blockIdx.x * MT;

    uint32_t sbase = (uint32_t)__cvta_generic_to_shared(smem);
    const uint32_t aOff = sbase + SM_A;
    const uint32_t bOff = sbase + SM_B;

    // LDSM lane addressing — byte-identical pattern to the verified f16 code
    const int aRow  = wm * 32 + (lane & 15);
    const int aColB = ((lane >> 4) & 1) * 16;       // byte offset
    const int bRow  = wn * 32 + (lane & 7) + ((lane >> 4) & 1) * 8;
    const int bColB = ((lane >> 3) & 1) * 16;       // byte offset

    const int g  = lane >> 2;
    const int qd = lane & 3;

    float x2v[2][2], cx[2][2];
#pragma unroll
    for (int mi = 0; mi < 2; mi++)
#pragma unroll
        for (int p = 0; p < 2; p++) {
            int r = m0 + wm * 32 + mi * 16 + g + p * 8;
            x2v[mi][p] = g_x2[r];
            cx[mi][p]  = -2.f * g_sx[r];
        }

    // ---- resident A load: 4 chunks x [128 rows x 128B] SW128 (full K=512 int8)
#pragma unroll
    for (int i = 0; i < 8; i++) {
        int c = tid + i * 512;                      // 4096 16B units
        int chunk = c >> 10, u = c & 1023;
        int row = u >> 3, seg = u & 7;
        uint32_t dst = aOff + (uint32_t)(chunk * 16384 + SWZ128(row * 128 + seg * 16));
        CP16(dst, g_A8 + (size_t)(m0 + row) * 512 + chunk * 128 + seg * 16);
    }
    CP_COMMIT();
    // ---- B ring prologue: stages 0,1,2 of tile 0
    b_stage(bOff, 0, 0, 0, tid); CP_COMMIT();
    b_stage(bOff, 1, 0, 1, tid); CP_COMMIT();
    b_stage(bOff, 2, 0, 2, tid); CP_COMMIT();

    float ql[2][2][6];
#pragma unroll
    for (int mi = 0; mi < 2; mi++)
#pragma unroll
        for (int p = 0; p < 2; p++)
#pragma unroll
            for (int j = 0; j < 6; j++) ql[mi][p][j] = INFINITY;

    int acc[2][4][4];
#pragma unroll
    for (int mi = 0; mi < 2; mi++)
#pragma unroll
        for (int ni = 0; ni < 4; ni++)
#pragma unroll
            for (int r = 0; r < 4; r++) acc[mi][ni][r] = 0;

    // ---- main loop: 128 tiles x 4 compile-time stages (K=128 int8 each) ----
    // gg = nt*4 + s ; slot = gg&3 = s ; A chunk = s. Prefetch gg+3: slot (s+3)&3,
    // k-chunk (s+3)&3, tile nt + ((s+3)>>2).
#pragma unroll 1
    for (int nt = 0; nt < NTILES; nt++) {
        const int mb = nt & 1;
        const int n0 = nt * NT;
        if (tid < 128) {
            m2s[mb * 128 + tid] = g_m2[n0 + tid];
            sms[mb * 128 + tid] = g_sm[n0 + tid];
        }

#pragma unroll
        for (int s = 0; s < 4; s++) {
            CP_WAIT(2);
            __syncthreads();

            const uint32_t bbuf = bOff + s * 16384;   // compile-time
            const uint32_t abuf = aOff + s * 16384;   // compile-time
#pragma unroll
            for (int kk = 0; kk < 128; kk += 32) {    // byte offsets within 128B rows
                uint32_t a[2][4], bf[4][2];
#pragma unroll
                for (int mi = 0; mi < 2; mi++) {
                    uint32_t ad = abuf + (uint32_t)SWZ128(((aRow + mi * 16) * 128 + kk + aColB));
                    LDSM4(a[mi][0], a[mi][1], a[mi][2], a[mi][3], ad);
                }
#pragma unroll
                for (int jp = 0; jp < 2; jp++) {
                    uint32_t bd = bbuf + (uint32_t)SWZ128(((bRow + jp * 16) * 128 + kk + bColB));
                    LDSM4(bf[2 * jp][0], bf[2 * jp][1], bf[2 * jp + 1][0], bf[2 * jp + 1][1], bd);
                }
#pragma unroll
                for (int mi = 0; mi < 2; mi++)
#pragma unroll
                    for (int ni = 0; ni < 4; ni++)
                        MMA16832_S8(acc[mi][ni], a[mi], bf[ni][0], bf[ni][1]);
            }

            // prefetch stage gg+3 (compile-time slot/k-chunk)
            {
                const int nt3 = nt + ((s + 3) >> 2);
                if (nt3 < NTILES)
                    b_stage(bOff, (s + 3) & 3, nt3 * NT, (s + 3) & 3, tid);
            }
            CP_COMMIT();

            if (s == 3) {
                // in-register epilogue: d2 = x2 + m2 - 2*sx*sm*dot
#pragma unroll
                for (int mi = 0; mi < 2; mi++)
#pragma unroll
                    for (int ni = 0; ni < 4; ni++) {
                        const int col = wn * 32 + ni * 8 + 2 * qd;
                        const float m20 = m2s[mb * 128 + col];
                        const float m21 = m2s[mb * 128 + col + 1];
                        const float s0 = sms[mb * 128 + col];
                        const float s1 = sms[mb * 128 + col + 1];
                        insert6a(fmaxf(fmaf(cx[mi][0] * s0, __int2float_rn(acc[mi][ni][0]), x2v[mi][0] + m20), 0.f), ql[mi][0]);
                        insert6a(fmaxf(fmaf(cx[mi][0] * s1, __int2float_rn(acc[mi][ni][1]), x2v[mi][0] + m21), 0.f), ql[mi][0]);
                        insert6a(fmaxf(fmaf(cx[mi][1] * s0, __int2float_rn(acc[mi][ni][2]), x2v[mi][1] + m20), 0.f), ql[mi][1]);
                        insert6a(fmaxf(fmaf(cx[mi][1] * s1, __int2float_rn(acc[mi][ni][3]), x2v[mi][1] + m21), 0.f), ql[mi][1]);
                        acc[mi][ni][0] = 0; acc[mi][ni][1] = 0;
                        acc[mi][ni][2] = 0; acc[mi][ni][3] = 0;
                    }
            }
        }
    }

    // ---- quad merge (same 4 rows within a quad), snapshot-before-insert
#pragma unroll
    for (int off = 2; off > 0; off >>= 1) {
#pragma unroll
        for (int mi = 0; mi < 2; mi++)
#pragma unroll
            for (int p = 0; p < 2; p++) {
                float t[6];
#pragma unroll
                for (int j = 0; j < 6; j++)
                    t[j] = __shfl_down_sync(0xffffffffu, ql[mi][p][j], off, 4);
#pragma unroll
                for (int j = 0; j < 6; j++) insert6a(t[j], ql[mi][p]);
            }
    }

    // ---- cross-warp merge staging: 4 N-warps per row, 6 values each
    if (qd == 0) {
#pragma unroll
        for (int mi = 0; mi < 2; mi++)
#pragma unroll
            for (int p = 0; p < 2; p++) {
                int r = wm * 32 + mi * 16 + g + p * 8;
#pragma unroll
                for (int j = 0; j < 6; j++)
                    stage[r * 24 + wn * 6 + j] = ql[mi][p][j];
            }
    }
    __syncthreads();

    float part = 0.f;
    if (tid < 128) {
        float f[6] = {INFINITY, INFINITY, INFINITY, INFINITY, INFINITY, INFINITY};
        const float* sr = stage + tid * 24;
#pragma unroll
        for (int i = 0; i < 24; i++) insert6a(sr[i], f);
        float rv = rptr[0];
        float r2 = rv * rv;
        part = fmaxf(f[0] - r2, 0.f) + fmaxf(f[1] - r2, 0.f) + fmaxf(f[2] - r2, 0.f)
             + fmaxf(r2 - f[3] - ALPHA_C, 0.f) + fmaxf(r2 - f[4] - ALPHA_C, 0.f)
             + fmaxf(r2 - f[5] - ALPHA_C, 0.f);
    }
    __syncthreads();
    float* red = stage;
    red[tid] = part;
    __syncthreads();
#pragma unroll
    for (int o = 256; o > 0; o >>= 1) {
        if (tid < o) red[tid] += red[tid + o];
        __syncthreads();
    }
    if (tid == 0) g_part[blockIdx.x] = red[0];
}

// Deterministic final reduction
__global__ void finalize_loss(float* __restrict__ out) {
    __shared__ float s[128];
    int t = threadIdx.x;
    s[t] = g_part[t];
    __syncthreads();
#pragma unroll
    for (int o = 64; o > 0; o >>= 1) {
        if (t < o) s[t] += s[t + o];
        __syncthreads();
    }
    if (t == 0) out[0] = s[0] * (1.0f / (49152.0f * NU_C));
}

// ---------------- launch ----------------
extern "C" void kernel_launch(void* const* d_in, const int* in_sizes, int n_in,
                              void* d_out, int out_size) {
    (void)in_sizes; (void)n_in; (void)out_size;
    const float* phi = (const float*)d_in[0];
    const float* mem = (const float*)d_in[1];
    const float* r   = (const float*)d_in[2];
    float* out = (float*)d_out;

    cudaFuncSetAttribute(knn_gemm, cudaFuncAttributeMaxDynamicSharedMemorySize, SMEM_BYTES);

    prep_phi<<<dim3(128, 16, 4), dim3(32, 8)>>>(phi);
    prep_xq<<<MDIM / 8, 256>>>();
    prep_mq<<<NDIM / 8, 256>>>(mem);
    knn_gemm<<<MDIM / MT, 512, SMEM_BYTES>>>(r);
    finalize_loss<<<1, 128>>>(out);
}

// round 14
// speedup vs baseline: 2.5018x; 2.5018x over previous
#include <cuda_runtime.h>
#include <cuda_bf16.h>
#include <cstdint>

// Problem constants
#define MDIM 16384
#define NDIM 16384
#define KDIM 512
#define ALPHA_C 0.1f
#define NU_C 1e-3f

#define MT 128
#define NT 64                        // per-half tile width
#define HTILES 128                   // 8192 / 64 tiles per half

// smem layout (bytes)
#define SM_A   0                     // 8 chunks x [128 x 128B] SW128 = 131072
#define SM_B   131072                // 2 halves x 4 slots x 8192 = 65536
#define SM_M2  196608                // [2 halves][2 mb][64] floats = 2048
#define SM_STG 198656                // 128 x 24 floats = 12288
#define SMEM_BYTES 210944

// Scratch
__device__ __align__(16) __nv_bfloat16 g_A [MDIM * KDIM];
__device__ __align__(16) __nv_bfloat16 g_Bm[NDIM * KDIM];
__device__ float g_x2[MDIM];
__device__ float g_m2[NDIM];
__device__ float g_part[MDIM / MT];

// ---------------- PTX helpers ----------------
#define CP16(dst, src) \
  asm volatile("cp.async.cg.shared.global [%0], [%1], 16;\n" :: "r"(dst), "l"(src))
#define CP_COMMIT() asm volatile("cp.async.commit_group;\n" ::: "memory")
#define CP_WAIT(n)  asm volatile("cp.async.wait_group %0;\n" :: "n"(n) : "memory")

#define BAR_HALF(id) asm volatile("bar.sync %0, 256;" :: "r"(id) : "memory")

#define LDSM4(R0, R1, R2, R3, ADDR) \
  asm volatile("ldmatrix.sync.aligned.m8n8.x4.shared.b16 {%0,%1,%2,%3}, [%4];" \
               : "=r"(R0), "=r"(R1), "=r"(R2), "=r"(R3) : "r"(ADDR))

#define MMA16816(C, A, B0, B1) \
  asm volatile("mma.sync.aligned.m16n8k16.row.col.f32.bf16.bf16.f32 " \
               "{%0,%1,%2,%3},{%4,%5,%6,%7},{%8,%9},{%0,%1,%2,%3};" \
               : "+f"((C)[0]), "+f"((C)[1]), "+f"((C)[2]), "+f"((C)[3]) \
               : "r"((A)[0]), "r"((A)[1]), "r"((A)[2]), "r"((A)[3]), \
                 "r"(B0), "r"(B1))

#define SWZ128(x) ((x) ^ (((x) >> 3) & 0x70))

// ---------------- Prep kernels ----------------
__global__ void prep_phi(const float* __restrict__ phi) {
    __shared__ float t[32][33];
    int b = blockIdx.z, c0 = blockIdx.y * 32, h0 = blockIdx.x * 32;
    int tx = threadIdx.x, ty = threadIdx.y;
    const float* p = phi + ((size_t)b * 512 + c0) * 4096 + h0;
#pragma unroll
    for (int i = 0; i < 4; i++)
        t[ty + 8 * i][tx] = p[(size_t)(ty + 8 * i) * 4096 + tx];
    __syncthreads();
#pragma unroll
    for (int i = 0; i < 4; i++) {
        int row = ty + 8 * i;
        g_A[((size_t)b * 4096 + h0 + row) * 512 + c0 + tx] = __float2bfloat16(t[tx][row]);
    }
}

__global__ void prep_x2(const float* __restrict__ phi) {
    int m = blockIdx.x * 256 + threadIdx.x;
    int b = m >> 12, hw = m & 4095;
    const float* p = phi + (size_t)b * 512 * 4096 + hw;
    float s = 0.f;
#pragma unroll 8
    for (int c = 0; c < 512; c++) { float v = p[(size_t)c * 4096]; s = fmaf(v, v, s); }
    g_x2[m] = s;
}

__global__ void prep_mem(const float* __restrict__ mem) {
    int row  = (blockIdx.x * 256 + threadIdx.x) >> 5;
    int lane = threadIdx.x & 31;
    const float* p = mem + (size_t)row * 512;
    __nv_bfloat16* q = g_Bm + (size_t)row * 512;
    float s = 0.f;
#pragma unroll
    for (int i = 0; i < 16; i++) {
        float v = p[lane + i * 32];
        q[lane + i * 32] = __float2bfloat16(v);
        s = fmaf(v, v, s);
    }
#pragma unroll
    for (int o = 16; o > 0; o >>= 1) s += __shfl_xor_sync(0xffffffffu, s, o);
    if (lane == 0) g_m2[row] = s;
}

// ---------------- Main fused kernel ----------------
__device__ __forceinline__ void insert6a(float v, float (&q)[6]) {
    if (v < q[5]) {
        q[5] = v;
        if (q[5] < q[4]) { float t = q[4]; q[4] = q[5]; q[5] = t;
            if (q[4] < q[3]) { t = q[3]; q[3] = q[4]; q[4] = t;
                if (q[3] < q[2]) { t = q[2]; q[2] = q[3]; q[3] = t;
                    if (q[2] < q[1]) { t = q[1]; q[1] = q[2]; q[2] = t;
                        if (q[1] < q[0]) { t = q[0]; q[0] = q[1]; q[1] = t; } } } } }
    }
}

// stage s (k-chunk of 64 bf16) of 64-row tile n0 into half's ring slot
__device__ __forceinline__ void b_stage(uint32_t bOffH, int slot, int n0, int s, int tidl) {
#pragma unroll
    for (int i = 0; i < 2; i++) {
        int c = tidl + i * 256;               // 512 16B-units: 64 rows x 8 segs
        int row = c >> 3, seg = c & 7;
        uint32_t dst = bOffH + (uint32_t)(slot * 8192 + SWZ128(row * 128 + seg * 16));
        CP16(dst, g_Bm + (size_t)(n0 + row) * KDIM + s * 64 + seg * 8);
    }
}

__global__ __launch_bounds__(512, 1)
void knn_gemm(const float* __restrict__ rptr) {
    extern __shared__ char smem[];
    float* m2s   = (float*)(smem + SM_M2);    // [half][mb][64]
    float* stage = (float*)(smem + SM_STG);

    const int tid  = threadIdx.x;
    const int lane = tid & 31;
    const int warp = tid >> 5;
    const int half = warp >> 3;               // 0/1
    const int wl   = warp & 7;
    const int wm   = wl & 3;                  // 4 warps along M
    const int wn   = wl >> 2;                 // 2 warps along N (within half)
    const int tidl = tid & 255;
    const int m0   = blockIdx.x * MT;
    const int nheadbase = half * 8192;        // this half's column base

    uint32_t sbase = (uint32_t)__cvta_generic_to_shared(smem);
    const uint32_t aOff  = sbase + SM_A;
    const uint32_t bOffH = sbase + SM_B + half * 32768;

    // ldmatrix lane mappings (verified R2/R4/R7/R8/R11)
    const int aRow    = wm * 32 + (lane & 15);
    const int aColSel = ((lane >> 4) & 1) * 8;
    const int bRow    = wn * 32 + (lane & 7) + ((lane >> 4) & 1) * 8;
    const int bColSel = ((lane >> 3) & 1) * 8;

    const int g  = lane >> 2;
    const int qd = lane & 3;

    float x2v[2][2];
#pragma unroll
    for (int mi = 0; mi < 2; mi++)
#pragma unroll
        for (int p = 0; p < 2; p++)
            x2v[mi][p] = g_x2[m0 + wm * 32 + mi * 16 + g + p * 8];

    // ---- resident A load (full CTA): 8 chunks x [128 x 128B] SW128
#pragma unroll
    for (int i = 0; i < 16; i++) {
        int c = tid + i * 512;
        int chunk = c >> 10, u = c & 1023;
        int row = u >> 3, seg = u & 7;
        uint32_t dst = aOff + (uint32_t)(chunk * 16384 + SWZ128(row * 128 + seg * 16));
        CP16(dst, g_A + (size_t)(m0 + row) * KDIM + chunk * 64 + seg * 8);
    }
    CP_COMMIT();
    // ---- per-half B ring prologue: stages 0,1,2 of this half's tile 0
    b_stage(bOffH, 0, nheadbase, 0, tidl); CP_COMMIT();
    b_stage(bOffH, 1, nheadbase, 1, tidl); CP_COMMIT();
    b_stage(bOffH, 2, nheadbase, 2, tidl); CP_COMMIT();

    // A must be fully visible to BOTH halves before mainloop
    CP_WAIT(3);
    __syncthreads();

    float ql[2][2][6];
#pragma unroll
    for (int mi = 0; mi < 2; mi++)
#pragma unroll
        for (int p = 0; p < 2; p++)
#pragma unroll
            for (int j = 0; j < 6; j++) ql[mi][p][j] = INFINITY;

    float acc[2][4][4];
#pragma unroll
    for (int mi = 0; mi < 2; mi++)
#pragma unroll
        for (int ni = 0; ni < 4; ni++)
#pragma unroll
            for (int r = 0; r < 4; r++) acc[mi][ni][r] = 0.f;

    const int barid = 1 + half;

    // ---- main loop: 128 tiles (64 cols each) x 8 compile-time stages ----
#pragma unroll 1
    for (int nt = 0; nt < HTILES; nt++) {
        const int mb = nt & 1;
        const int n0 = nheadbase + nt * NT;
        if (tidl < 64) m2s[half * 128 + mb * 64 + tidl] = g_m2[n0 + tidl];

#pragma unroll
        for (int s = 0; s < 8; s++) {
            CP_WAIT(2);
            BAR_HALF(barid);

            const uint32_t bbuf = bOffH + (s & 3) * 8192;   // compile-time offset
            const uint32_t abuf = aOff + s * 16384;         // compile-time offset
#pragma unroll
            for (int kk = 0; kk < 64; kk += 16) {
                uint32_t a[2][4], bf[4][2];
#pragma unroll
                for (int mi = 0; mi < 2; mi++) {
                    uint32_t ad = abuf + (uint32_t)SWZ128(((aRow + mi * 16) * 128 + (kk + aColSel) * 2));
                    LDSM4(a[mi][0], a[mi][1], a[mi][2], a[mi][3], ad);
                }
#pragma unroll
                for (int jp = 0; jp < 2; jp++) {
                    uint32_t bd = bbuf + (uint32_t)SWZ128(((bRow + jp * 16) * 128 + (kk + bColSel) * 2));
                    LDSM4(bf[2 * jp][0], bf[2 * jp][1], bf[2 * jp + 1][0], bf[2 * jp + 1][1], bd);
                }
#pragma unroll
                for (int mi = 0; mi < 2; mi++)
#pragma unroll
                    for (int ni = 0; ni < 4; ni++)
                        MMA16816(acc[mi][ni], a[mi], bf[ni][0], bf[ni][1]);
            }

            // prefetch stage gg+3 of this half (compile-time slot/stage)
            {
                const int nt3 = nt + ((s + 3) >> 3);
                if (nt3 < HTILES)
                    b_stage(bOffH, (s + 3) & 3, nheadbase + nt3 * NT, (s + 3) & 7, tidl);
            }
            CP_COMMIT();

            if (s == 7) {
                // in-register epilogue: 16 distances into 4 running lists
#pragma unroll
                for (int mi = 0; mi < 2; mi++)
#pragma unroll
                    for (int ni = 0; ni < 4; ni++) {
                        const int col = wn * 32 + ni * 8 + 2 * qd;   // 0..63 in tile
                        const float m20 = m2s[half * 128 + mb * 64 + col];
                        const float m21 = m2s[half * 128 + mb * 64 + col + 1];
                        insert6a(fmaxf(fmaf(-2.f, acc[mi][ni][0], x2v[mi][0] + m20), 0.f), ql[mi][0]);
                        insert6a(fmaxf(fmaf(-2.f, acc[mi][ni][1], x2v[mi][0] + m21), 0.f), ql[mi][0]);
                        insert6a(fmaxf(fmaf(-2.f, acc[mi][ni][2], x2v[mi][1] + m20), 0.f), ql[mi][1]);
                        insert6a(fmaxf(fmaf(-2.f, acc[mi][ni][3], x2v[mi][1] + m21), 0.f), ql[mi][1]);
                        acc[mi][ni][0] = 0.f; acc[mi][ni][1] = 0.f;
                        acc[mi][ni][2] = 0.f; acc[mi][ni][3] = 0.f;
                    }
            }
        }
    }

    // ---- quad merge (same 4 rows within a quad), snapshot-before-insert
#pragma unroll
    for (int off = 2; off > 0; off >>= 1) {
#pragma unroll
        for (int mi = 0; mi < 2; mi++)
#pragma unroll
            for (int p = 0; p < 2; p++) {
                float t[6];
#pragma unroll
                for (int j = 0; j < 6; j++)
                    t[j] = __shfl_down_sync(0xffffffffu, ql[mi][p][j], off, 4);
#pragma unroll
                for (int j = 0; j < 6; j++) insert6a(t[j], ql[mi][p]);
            }
    }

    // ---- cross merge staging: 4 lists/row = (half,wn), 6 values each
    if (qd == 0) {
        const int sl = half * 2 + wn;         // 0..3
#pragma unroll
        for (int mi = 0; mi < 2; mi++)
#pragma unroll
            for (int p = 0; p < 2; p++) {
                int r = wm * 32 + mi * 16 + g + p * 8;
#pragma unroll
                for (int j = 0; j < 6; j++)
                    stage[r * 24 + sl * 6 + j] = ql[mi][p][j];
            }
    }
    __syncthreads();

    float part = 0.f;
    if (tid < 128) {
        float f[6] = {INFINITY, INFINITY, INFINITY, INFINITY, INFINITY, INFINITY};
        const float* sr = stage + tid * 24;
#pragma unroll
        for (int i = 0; i < 24; i++) insert6a(sr[i], f);
        float rv = rptr[0];
        float r2 = rv * rv;
        part = fmaxf(f[0] - r2, 0.f) + fmaxf(f[1] - r2, 0.f) + fmaxf(f[2] - r2, 0.f)
             + fmaxf(r2 - f[3] - ALPHA_C, 0.f) + fmaxf(r2 - f[4] - ALPHA_C, 0.f)
             + fmaxf(r2 - f[5] - ALPHA_C, 0.f);
    }
    __syncthreads();
    float* red = stage;
    red[tid] = part;
    __syncthreads();
#pragma unroll
    for (int o = 256; o > 0; o >>= 1) {
        if (tid < o) red[tid] += red[tid + o];
        __syncthreads();
    }
    if (tid == 0) g_part[blockIdx.x] = red[0];
}

// Deterministic final reduction
__global__ void finalize_loss(float* __restrict__ out) {
    __shared__ float s[128];
    int t = threadIdx.x;
    s[t] = g_part[t];
    __syncthreads();
#pragma unroll
    for (int o = 64; o > 0; o >>= 1) {
        if (t < o) s[t] += s[t + o];
        __syncthreads();
    }
    if (t == 0) out[0] = s[0] * (1.0f / (49152.0f * NU_C));
}

// ---------------- launch ----------------
extern "C" void kernel_launch(void* const* d_in, const int* in_sizes, int n_in,
                              void* d_out, int out_size) {
    (void)in_sizes; (void)n_in; (void)out_size;
    const float* phi = (const float*)d_in[0];
    const float* mem = (const float*)d_in[1];
    const float* r   = (const float*)d_in[2];
    float* out = (float*)d_out;

    cudaFuncSetAttribute(knn_gemm, cudaFuncAttributeMaxDynamicSharedMemorySize, SMEM_BYTES);

    prep_phi<<<dim3(128, 16, 4), dim3(32, 8)>>>(phi);
    prep_x2<<<MDIM / 256, 256>>>(phi);
    prep_mem<<<NDIM / 8, 256>>>(mem);
    knn_gemm<<<MDIM / MT, 512, SMEM_BYTES>>>(r);
    finalize_loss<<<1, 128>>>(out);
}

// round 15
// speedup vs baseline: 2.5340x; 1.0129x over previous
#include <cuda_runtime.h>
#include <cuda_bf16.h>
#include <cstdint>

// Problem constants
#define MDIM 16384
#define NDIM 16384
#define KDIM 512
#define ALPHA_C 0.1f
#define NU_C 1e-3f

#define MT 128
#define NT 64                        // per-half tile width
#define HTILES 128                   // 8192 / 64 tiles per half

// smem layout (bytes)
#define SM_A   0                     // 8 chunks x [128 x 128B] SW128 = 131072
#define SM_B   131072                // 2 halves x 4 slots x 8192 = 65536
#define SM_M2  196608                // [2 halves][2 mb][64] floats = 2048
#define SM_STG 198656                // 128 x 24 floats = 12288
#define SMEM_BYTES 210944

// Scratch
__device__ __align__(16) __nv_bfloat16 g_A [MDIM * KDIM];
__device__ __align__(16) __nv_bfloat16 g_Bm[NDIM * KDIM];
__device__ float g_x2[MDIM];
__device__ float g_m2[NDIM];
__device__ float g_part[MDIM / MT];

// ---------------- PTX helpers ----------------
#define CP16(dst, src) \
  asm volatile("cp.async.cg.shared.global [%0], [%1], 16;\n" :: "r"(dst), "l"(src))
#define CP_COMMIT() asm volatile("cp.async.commit_group;\n" ::: "memory")
#define CP_WAIT(n)  asm volatile("cp.async.wait_group %0;\n" :: "n"(n) : "memory")

#define BAR_HALF(id) asm volatile("bar.sync %0, 256;" :: "r"(id) : "memory")

#define LDSM4(R0, R1, R2, R3, ADDR) \
  asm volatile("ldmatrix.sync.aligned.m8n8.x4.shared.b16 {%0,%1,%2,%3}, [%4];" \
               : "=r"(R0), "=r"(R1), "=r"(R2), "=r"(R3) : "r"(ADDR))

#define MMA16816(C, A, B0, B1) \
  asm volatile("mma.sync.aligned.m16n8k16.row.col.f32.bf16.bf16.f32 " \
               "{%0,%1,%2,%3},{%4,%5,%6,%7},{%8,%9},{%0,%1,%2,%3};" \
               : "+f"((C)[0]), "+f"((C)[1]), "+f"((C)[2]), "+f"((C)[3]) \
               : "r"((A)[0]), "r"((A)[1]), "r"((A)[2]), "r"((A)[3]), \
                 "r"(B0), "r"(B1))

#define SWZ128(x) ((x) ^ (((x) >> 3) & 0x70))

// ---------------- Prep kernels ----------------
// Fused transpose + x2: one block owns 32 hw-rows x all 512 channels.
// grid (128, 4): blockIdx.x = hw block, blockIdx.y = b. block (32, 8).
__global__ void prep_phi_x2(const float* __restrict__ phi) {
    __shared__ float t[32][33];
    __shared__ float x2s[32];
    const int b = blockIdx.y, h0 = blockIdx.x * 32;
    const int tx = threadIdx.x, ty = threadIdx.y;
    const int tid = tx + ty * 32;
    if (tid < 32) x2s[tid] = 0.f;
    __syncthreads();

#pragma unroll 1
    for (int cb = 0; cb < 16; cb++) {
        const int c0 = cb * 32;
        const float* p = phi + ((size_t)b * 512 + c0) * 4096 + h0;
#pragma unroll
        for (int i = 0; i < 4; i++)
            t[ty + 8 * i][tx] = p[(size_t)(ty + 8 * i) * 4096 + tx];
        __syncthreads();
#pragma unroll
        for (int i = 0; i < 4; i++) {
            int row = ty + 8 * i;                 // hw-local row
            float v = t[tx][row];                 // channel c0+tx of this row
            g_A[((size_t)b * 4096 + h0 + row) * 512 + c0 + tx] = __float2bfloat16(v);
            // warp (ty) lanes tx=0..31 all hold row's channels -> reduce v^2
            float sq = v * v;
#pragma unroll
            for (int o = 16; o > 0; o >>= 1) sq += __shfl_xor_sync(0xffffffffu, sq, o);
            if (tx == 0) x2s[row] += sq;          // single writer per row per chunk
        }
        __syncthreads();
    }
    if (tid < 32) g_x2[(size_t)b * 4096 + h0 + tid] = x2s[tid];
}

__global__ void prep_mem(const float* __restrict__ mem) {
    int row  = (blockIdx.x * 256 + threadIdx.x) >> 5;
    int lane = threadIdx.x & 31;
    const float* p = mem + (size_t)row * 512;
    __nv_bfloat16* q = g_Bm + (size_t)row * 512;
    float s = 0.f;
#pragma unroll
    for (int i = 0; i < 16; i++) {
        float v = p[lane + i * 32];
        q[lane + i * 32] = __float2bfloat16(v);
        s = fmaf(v, v, s);
    }
#pragma unroll
    for (int o = 16; o > 0; o >>= 1) s += __shfl_xor_sync(0xffffffffu, s, o);
    if (lane == 0) g_m2[row] = s;
}

// ---------------- Main fused kernel ----------------
__device__ __forceinline__ void insert6a(float v, float (&q)[6]) {
    if (v < q[5]) {
        q[5] = v;
        if (q[5] < q[4]) { float t = q[4]; q[4] = q[5]; q[5] = t;
            if (q[4] < q[3]) { t = q[3]; q[3] = q[4]; q[4] = t;
                if (q[3] < q[2]) { t = q[2]; q[2] = q[3]; q[3] = t;
                    if (q[2] < q[1]) { t = q[1]; q[1] = q[2]; q[2] = t;
                        if (q[1] < q[0]) { t = q[0]; q[0] = q[1]; q[1] = t; } } } } }
    }
}

// stage s (k-chunk of 64 bf16) of 64-row tile n0 into half's ring slot
__device__ __forceinline__ void b_stage(uint32_t bOffH, int slot, int n0, int s, int tidl) {
#pragma unroll
    for (int i = 0; i < 2; i++) {
        int c = tidl + i * 256;               // 512 16B-units: 64 rows x 8 segs
        int row = c >> 3, seg = c & 7;
        uint32_t dst = bOffH + (uint32_t)(slot * 8192 + SWZ128(row * 128 + seg * 16));
        CP16(dst, g_Bm + (size_t)(n0 + row) * KDIM + s * 64 + seg * 8);
    }
}

__global__ __launch_bounds__(512, 1)
void knn_gemm(const float* __restrict__ rptr) {
    extern __shared__ char smem[];
    float* m2s   = (float*)(smem + SM_M2);    // [half][mb][64]
    float* stage = (float*)(smem + SM_STG);

    const int tid  = threadIdx.x;
    const int lane = tid & 31;
    const int warp = tid >> 5;
    const int half = warp >> 3;               // 0/1
    const int wl   = warp & 7;
    const int wm   = wl & 3;                  // 4 warps along M
    const int wn   = wl >> 2;                 // 2 warps along N (within half)
    const int tidl = tid & 255;
    const int m0   = blockIdx.x * MT;
    const int nheadbase = half * 8192;        // this half's column base

    uint32_t sbase = (uint32_t)__cvta_generic_to_shared(smem);
    const uint32_t aOff  = sbase + SM_A;
    const uint32_t bOffH = sbase + SM_B + half * 32768;

    // ldmatrix lane mappings (verified R2/R4/R7/R8/R11/R14)
    const int aRow    = wm * 32 + (lane & 15);
    const int aColSel = ((lane >> 4) & 1) * 8;
    const int bRow    = wn * 32 + (lane & 7) + ((lane >> 4) & 1) * 8;
    const int bColSel = ((lane >> 3) & 1) * 8;

    const int g  = lane >> 2;
    const int qd = lane & 3;

    float x2v[2][2];
#pragma unroll
    for (int mi = 0; mi < 2; mi++)
#pragma unroll
        for (int p = 0; p < 2; p++)
            x2v[mi][p] = g_x2[m0 + wm * 32 + mi * 16 + g + p * 8];

    // ---- resident A load (full CTA): 8 chunks x [128 x 128B] SW128
#pragma unroll
    for (int i = 0; i < 16; i++) {
        int c = tid + i * 512;
        int chunk = c >> 10, u = c & 1023;
        int row = u >> 3, seg = u & 7;
        uint32_t dst = aOff + (uint32_t)(chunk * 16384 + SWZ128(row * 128 + seg * 16));
        CP16(dst, g_A + (size_t)(m0 + row) * KDIM + chunk * 64 + seg * 8);
    }
    CP_COMMIT();
    // ---- per-half B ring prologue: stages 0,1,2 of this half's tile 0
    b_stage(bOffH, 0, nheadbase, 0, tidl); CP_COMMIT();
    b_stage(bOffH, 1, nheadbase, 1, tidl); CP_COMMIT();
    b_stage(bOffH, 2, nheadbase, 2, tidl); CP_COMMIT();

    // A must be fully visible to BOTH halves before mainloop
    CP_WAIT(3);
    __syncthreads();

    float ql[2][2][6];
#pragma unroll
    for (int mi = 0; mi < 2; mi++)
#pragma unroll
        for (int p = 0; p < 2; p++)
#pragma unroll
            for (int j = 0; j < 6; j++) ql[mi][p][j] = INFINITY;

    float acc[2][4][4];
#pragma unroll
    for (int mi = 0; mi < 2; mi++)
#pragma unroll
        for (int ni = 0; ni < 4; ni++)
#pragma unroll
            for (int r = 0; r < 4; r++) acc[mi][ni][r] = 0.f;

    const int barid = 1 + half;

    // ---- main loop: 128 tiles (64 cols each) x 8 compile-time stages ----
#pragma unroll 1
    for (int nt = 0; nt < HTILES; nt++) {
        const int mb = nt & 1;
        const int n0 = nheadbase + nt * NT;
        if (tidl < 64) m2s[half * 128 + mb * 64 + tidl] = g_m2[n0 + tidl];

#pragma unroll
        for (int s = 0; s < 8; s++) {
            CP_WAIT(2);
            BAR_HALF(barid);

            const uint32_t bbuf = bOffH + (s & 3) * 8192;   // compile-time offset
            const uint32_t abuf = aOff + s * 16384;         // compile-time offset
#pragma unroll
            for (int kk = 0; kk < 64; kk += 16) {
                uint32_t a[2][4], bf[4][2];
#pragma unroll
                for (int mi = 0; mi < 2; mi++) {
                    uint32_t ad = abuf + (uint32_t)SWZ128(((aRow + mi * 16) * 128 + (kk + aColSel) * 2));
                    LDSM4(a[mi][0], a[mi][1], a[mi][2], a[mi][3], ad);
                }
#pragma unroll
                for (int jp = 0; jp < 2; jp++) {
                    uint32_t bd = bbuf + (uint32_t)SWZ128(((bRow + jp * 16) * 128 + (kk + bColSel) * 2));
                    LDSM4(bf[2 * jp][0], bf[2 * jp][1], bf[2 * jp + 1][0], bf[2 * jp + 1][1], bd);
                }
#pragma unroll
                for (int mi = 0; mi < 2; mi++)
#pragma unroll
                    for (int ni = 0; ni < 4; ni++)
                        MMA16816(acc[mi][ni], a[mi], bf[ni][0], bf[ni][1]);
            }

            // prefetch stage gg+3 of this half (compile-time slot/stage)
            {
                const int nt3 = nt + ((s + 3) >> 3);
                if (nt3 < HTILES)
                    b_stage(bOffH, (s + 3) & 3, nheadbase + nt3 * NT, (s + 3) & 7, tidl);
            }
            CP_COMMIT();

            if (s == 7) {
                // in-register epilogue: 16 distances into 4 running lists
#pragma unroll
                for (int mi = 0; mi < 2; mi++)
#pragma unroll
                    for (int ni = 0; ni < 4; ni++) {
                        const int col = wn * 32 + ni * 8 + 2 * qd;   // 0..63 in tile
                        const float m20 = m2s[half * 128 + mb * 64 + col];
                        const float m21 = m2s[half * 128 + mb * 64 + col + 1];
                        insert6a(fmaxf(fmaf(-2.f, acc[mi][ni][0], x2v[mi][0] + m20), 0.f), ql[mi][0]);
                        insert6a(fmaxf(fmaf(-2.f, acc[mi][ni][1], x2v[mi][0] + m21), 0.f), ql[mi][0]);
                        insert6a(fmaxf(fmaf(-2.f, acc[mi][ni][2], x2v[mi][1] + m20), 0.f), ql[mi][1]);
                        insert6a(fmaxf(fmaf(-2.f, acc[mi][ni][3], x2v[mi][1] + m21), 0.f), ql[mi][1]);
                        acc[mi][ni][0] = 0.f; acc[mi][ni][1] = 0.f;
                        acc[mi][ni][2] = 0.f; acc[mi][ni][3] = 0.f;
                    }
            }
        }
    }

    // ---- quad merge (same 4 rows within a quad), snapshot-before-insert
#pragma unroll
    for (int off = 2; off > 0; off >>= 1) {
#pragma unroll
        for (int mi = 0; mi < 2; mi++)
#pragma unroll
            for (int p = 0; p < 2; p++) {
                float t[6];
#pragma unroll
                for (int j = 0; j < 6; j++)
                    t[j] = __shfl_down_sync(0xffffffffu, ql[mi][p][j], off, 4);
#pragma unroll
                for (int j = 0; j < 6; j++) insert6a(t[j], ql[mi][p]);
            }
    }

    // ---- cross merge staging: 4 lists/row = (half,wn), 6 values each
    if (qd == 0) {
        const int sl = half * 2 + wn;         // 0..3
#pragma unroll
        for (int mi = 0; mi < 2; mi++)
#pragma unroll
            for (int p = 0; p < 2; p++) {
                int r = wm * 32 + mi * 16 + g + p * 8;
#pragma unroll
                for (int j = 0; j < 6; j++)
                    stage[r * 24 + sl * 6 + j] = ql[mi][p][j];
            }
    }
    __syncthreads();

    float part = 0.f;
    if (tid < 128) {
        float f[6] = {INFINITY, INFINITY, INFINITY, INFINITY, INFINITY, INFINITY};
        const float* sr = stage + tid * 24;
#pragma unroll
        for (int i = 0; i < 24; i++) insert6a(sr[i], f);
        float rv = rptr[0];
        float r2 = rv * rv;
        part = fmaxf(f[0] - r2, 0.f) + fmaxf(f[1] - r2, 0.f) + fmaxf(f[2] - r2, 0.f)
             + fmaxf(r2 - f[3] - ALPHA_C, 0.f) + fmaxf(r2 - f[4] - ALPHA_C, 0.f)
             + fmaxf(r2 - f[5] - ALPHA_C, 0.f);
    }
    __syncthreads();
    float* red = stage;
    red[tid] = part;
    __syncthreads();
#pragma unroll
    for (int o = 256; o > 0; o >>= 1) {
        if (tid < o) red[tid] += red[tid + o];
        __syncthreads();
    }
    if (tid == 0) g_part[blockIdx.x] = red[0];
}

// Deterministic final reduction
__global__ void finalize_loss(float* __restrict__ out) {
    __shared__ float s[128];
    int t = threadIdx.x;
    s[t] = g_part[t];
    __syncthreads();
#pragma unroll
    for (int o = 64; o > 0; o >>= 1) {
        if (t < o) s[t] += s[t + o];
        __syncthreads();
    }
    if (t == 0) out[0] = s[0] * (1.0f / (49152.0f * NU_C));
}

// ---------------- launch ----------------
extern "C" void kernel_launch(void* const* d_in, const int* in_sizes, int n_in,
                              void* d_out, int out_size) {
    (void)in_sizes; (void)n_in; (void)out_size;
    const float* phi = (const float*)d_in[0];
    const float* mem = (const float*)d_in[1];
    const float* r   = (const float*)d_in[2];
    float* out = (float*)d_out;

    cudaFuncSetAttribute(knn_gemm, cudaFuncAttributeMaxDynamicSharedMemorySize, SMEM_BYTES);

    prep_phi_x2<<<dim3(128, 4), dim3(32, 8)>>>(phi);
    prep_mem<<<NDIM / 8, 256>>>(mem);
    knn_gemm<<<MDIM / MT, 512, SMEM_BYTES>>>(r);
    finalize_loss<<<1, 128>>>(out);
}

// round 16
// speedup vs baseline: 2.6601x; 1.0498x over previous
#include <cuda_runtime.h>
#include <cuda_bf16.h>
#include <cstdint>

// Problem constants
#define MDIM 16384
#define NDIM 16384
#define KDIM 512
#define ALPHA_C 0.1f
#define NU_C 1e-3f

#define MT 128
#define NT 32                        // per-quarter tile width
#define QTILES 128                   // 4096 / 32 tiles per quarter

// smem layout (bytes)
#define SM_A   0                     // 8 chunks x [128 x 128B] SW128 = 131072
#define SM_B   131072                // 4 quarters x 4 slots x 4096 = 65536
#define SM_M2  196608                // [4 quarters][2 mb][32] floats = 1024
#define SM_STG 197632                // 128 x 24 floats = 12288
#define SMEM_BYTES 209920

// Scratch
__device__ __align__(16) __nv_bfloat16 g_A [MDIM * KDIM];
__device__ __align__(16) __nv_bfloat16 g_Bm[NDIM * KDIM];
__device__ float g_x2[MDIM];
__device__ float g_m2[NDIM];
__device__ float g_part[MDIM / MT];

// ---------------- PTX helpers ----------------
#define CP16(dst, src) \
  asm volatile("cp.async.cg.shared.global [%0], [%1], 16;\n" :: "r"(dst), "l"(src))
#define CP_COMMIT() asm volatile("cp.async.commit_group;\n" ::: "memory")
#define CP_WAIT(n)  asm volatile("cp.async.wait_group %0;\n" :: "n"(n) : "memory")

#define BAR_Q(id) asm volatile("bar.sync %0, 128;" :: "r"(id) : "memory")

#define LDSM4(R0, R1, R2, R3, ADDR) \
  asm volatile("ldmatrix.sync.aligned.m8n8.x4.shared.b16 {%0,%1,%2,%3}, [%4];" \
               : "=r"(R0), "=r"(R1), "=r"(R2), "=r"(R3) : "r"(ADDR))

#define MMA16816(C, A, B0, B1) \
  asm volatile("mma.sync.aligned.m16n8k16.row.col.f32.bf16.bf16.f32 " \
               "{%0,%1,%2,%3},{%4,%5,%6,%7},{%8,%9},{%0,%1,%2,%3};" \
               : "+f"((C)[0]), "+f"((C)[1]), "+f"((C)[2]), "+f"((C)[3]) \
               : "r"((A)[0]), "r"((A)[1]), "r"((A)[2]), "r"((A)[3]), \
                 "r"(B0), "r"(B1))

#define SWZ128(x) ((x) ^ (((x) >> 3) & 0x70))

// ---------------- Prep kernels ----------------
// Fused transpose + x2: one block owns 32 hw-rows x all 512 channels.
__global__ void prep_phi_x2(const float* __restrict__ phi) {
    __shared__ float t[32][33];
    __shared__ float x2s[32];
    const int b = blockIdx.y, h0 = blockIdx.x * 32;
    const int tx = threadIdx.x, ty = threadIdx.y;
    const int tid = tx + ty * 32;
    if (tid < 32) x2s[tid] = 0.f;
    __syncthreads();

#pragma unroll 1
    for (int cb = 0; cb < 16; cb++) {
        const int c0 = cb * 32;
        const float* p = phi + ((size_t)b * 512 + c0) * 4096 + h0;
#pragma unroll
        for (int i = 0; i < 4; i++)
            t[ty + 8 * i][tx] = p[(size_t)(ty + 8 * i) * 4096 + tx];
        __syncthreads();
#pragma unroll
        for (int i = 0; i < 4; i++) {
            int row = ty + 8 * i;
            float v = t[tx][row];
            g_A[((size_t)b * 4096 + h0 + row) * 512 + c0 + tx] = __float2bfloat16(v);
            float sq = v * v;
#pragma unroll
            for (int o = 16; o > 0; o >>= 1) sq += __shfl_xor_sync(0xffffffffu, sq, o);
            if (tx == 0) x2s[row] += sq;
        }
        __syncthreads();
    }
    if (tid < 32) g_x2[(size_t)b * 4096 + h0 + tid] = x2s[tid];
}

__global__ void prep_mem(const float* __restrict__ mem) {
    int row  = (blockIdx.x * 256 + threadIdx.x) >> 5;
    int lane = threadIdx.x & 31;
    const float* p = mem + (size_t)row * 512;
    __nv_bfloat16* q = g_Bm + (size_t)row * 512;
    float s = 0.f;
#pragma unroll
    for (int i = 0; i < 16; i++) {
        float v = p[lane + i * 32];
        q[lane + i * 32] = __float2bfloat16(v);
        s = fmaf(v, v, s);
    }
#pragma unroll
    for (int o = 16; o > 0; o >>= 1) s += __shfl_xor_sync(0xffffffffu, s, o);
    if (lane == 0) g_m2[row] = s;
}

// ---------------- Main fused kernel ----------------
__device__ __forceinline__ void insert6a(float v, float (&q)[6]) {
    if (v < q[5]) {
        q[5] = v;
        if (q[5] < q[4]) { float t = q[4]; q[4] = q[5]; q[5] = t;
            if (q[4] < q[3]) { t = q[3]; q[3] = q[4]; q[4] = t;
                if (q[3] < q[2]) { t = q[2]; q[2] = q[3]; q[3] = t;
                    if (q[2] < q[1]) { t = q[1]; q[1] = q[2]; q[2] = t;
                        if (q[1] < q[0]) { t = q[0]; q[0] = q[1]; q[1] = t; } } } } }
    }
}

// stage s (k-chunk of 64 bf16) of 32-row tile n0 into quarter's ring slot
__device__ __forceinline__ void b_stage(uint32_t bOffQ, int slot, int n0, int s, int tidq) {
#pragma unroll
    for (int i = 0; i < 2; i++) {
        int c = tidq + i * 128;               // 256 16B-units: 32 rows x 8 segs
        int row = c >> 3, seg = c & 7;
        uint32_t dst = bOffQ + (uint32_t)(slot * 4096 + SWZ128(row * 128 + seg * 16));
        CP16(dst, g_Bm + (size_t)(n0 + row) * KDIM + s * 64 + seg * 8);
    }
}

__global__ __launch_bounds__(512, 1)
void knn_gemm(const float* __restrict__ rptr) {
    extern __shared__ char smem[];
    float* m2s   = (float*)(smem + SM_M2);    // [quarter][mb][32]
    float* stage = (float*)(smem + SM_STG);

    const int tid  = threadIdx.x;
    const int lane = tid & 31;
    const int warp = tid >> 5;
    const int qtr  = warp >> 2;               // 0..3
    const int wm   = warp & 3;                // 4 warps along M within quarter
    const int tidq = tid & 127;
    const int m0   = blockIdx.x * MT;
    const int nqbase = qtr * 4096;            // this quarter's column base

    uint32_t sbase = (uint32_t)__cvta_generic_to_shared(smem);
    const uint32_t aOff  = sbase + SM_A;
    const uint32_t bOffQ = sbase + SM_B + qtr * 16384;

    // ldmatrix lane mappings (verified R2..R15); B tile is 32 rows -> no wn offset
    const int aRow    = wm * 32 + (lane & 15);
    const int aColSel = ((lane >> 4) & 1) * 8;
    const int bRow    = (lane & 7) + ((lane >> 4) & 1) * 8;
    const int bColSel = ((lane >> 3) & 1) * 8;

    const int g  = lane >> 2;
    const int qd = lane & 3;

    float x2v[2][2];
#pragma unroll
    for (int mi = 0; mi < 2; mi++)
#pragma unroll
        for (int p = 0; p < 2; p++)
            x2v[mi][p] = g_x2[m0 + wm * 32 + mi * 16 + g + p * 8];

    // ---- resident A load (full CTA): 8 chunks x [128 x 128B] SW128
#pragma unroll
    for (int i = 0; i < 16; i++) {
        int c = tid + i * 512;
        int chunk = c >> 10, u = c & 1023;
        int row = u >> 3, seg = u & 7;
        uint32_t dst = aOff + (uint32_t)(chunk * 16384 + SWZ128(row * 128 + seg * 16));
        CP16(dst, g_A + (size_t)(m0 + row) * KDIM + chunk * 64 + seg * 8);
    }
    CP_COMMIT();
    // ---- per-quarter B ring prologue: stages 0,1,2 of quarter's tile 0
    b_stage(bOffQ, 0, nqbase, 0, tidq); CP_COMMIT();
    b_stage(bOffQ, 1, nqbase, 1, tidq); CP_COMMIT();
    b_stage(bOffQ, 2, nqbase, 2, tidq); CP_COMMIT();

    // A must be fully visible to ALL quarters before mainloop
    CP_WAIT(3);
    __syncthreads();

    float ql[2][2][6];
#pragma unroll
    for (int mi = 0; mi < 2; mi++)
#pragma unroll
        for (int p = 0; p < 2; p++)
#pragma unroll
            for (int j = 0; j < 6; j++) ql[mi][p][j] = INFINITY;

    float acc[2][4][4];
#pragma unroll
    for (int mi = 0; mi < 2; mi++)
#pragma unroll
        for (int ni = 0; ni < 4; ni++)
#pragma unroll
            for (int r = 0; r < 4; r++) acc[mi][ni][r] = 0.f;

    const int barid = 1 + qtr;

    // ---- main loop: 128 tiles (32 cols each) x 8 compile-time stages ----
#pragma unroll 1
    for (int nt = 0; nt < QTILES; nt++) {
        const int mb = nt & 1;
        const int n0 = nqbase + nt * NT;
        if (tidq < 32) m2s[qtr * 64 + mb * 32 + tidq] = g_m2[n0 + tidq];

#pragma unroll
        for (int s = 0; s < 8; s++) {
            CP_WAIT(2);
            BAR_Q(barid);

            const uint32_t bbuf = bOffQ + (s & 3) * 4096;   // compile-time offset
            const uint32_t abuf = aOff + s * 16384;         // compile-time offset
#pragma unroll
            for (int kk = 0; kk < 64; kk += 16) {
                uint32_t a[2][4], bf[4][2];
#pragma unroll
                for (int mi = 0; mi < 2; mi++) {
                    uint32_t ad = abuf + (uint32_t)SWZ128(((aRow + mi * 16) * 128 + (kk + aColSel) * 2));
                    LDSM4(a[mi][0], a[mi][1], a[mi][2], a[mi][3], ad);
                }
#pragma unroll
                for (int jp = 0; jp < 2; jp++) {
                    uint32_t bd = bbuf + (uint32_t)SWZ128(((bRow + jp * 16) * 128 + (kk + bColSel) * 2));
                    LDSM4(bf[2 * jp][0], bf[2 * jp][1], bf[2 * jp + 1][0], bf[2 * jp + 1][1], bd);
                }
#pragma unroll
                for (int mi = 0; mi < 2; mi++)
#pragma unroll
                    for (int ni = 0; ni < 4; ni++)
                        MMA16816(acc[mi][ni], a[mi], bf[ni][0], bf[ni][1]);
            }

            // prefetch stage gg+3 of this quarter (compile-time slot/stage)
            {
                const int nt3 = nt + ((s + 3) >> 3);
                if (nt3 < QTILES)
                    b_stage(bOffQ, (s + 3) & 3, nqbase + nt3 * NT, (s + 3) & 7, tidq);
            }
            CP_COMMIT();

            if (s == 7) {
                // in-register epilogue: 16 distances into 4 running lists
#pragma unroll
                for (int mi = 0; mi < 2; mi++)
#pragma unroll
                    for (int ni = 0; ni < 4; ni++) {
                        const int col = ni * 8 + 2 * qd;             // 0..31 in tile
                        const float m20 = m2s[qtr * 64 + mb * 32 + col];
                        const float m21 = m2s[qtr * 64 + mb * 32 + col + 1];
                        insert6a(fmaxf(fmaf(-2.f, acc[mi][ni][0], x2v[mi][0] + m20), 0.f), ql[mi][0]);
                        insert6a(fmaxf(fmaf(-2.f, acc[mi][ni][1], x2v[mi][0] + m21), 0.f), ql[mi][0]);
                        insert6a(fmaxf(fmaf(-2.f, acc[mi][ni][2], x2v[mi][1] + m20), 0.f), ql[mi][1]);
                        insert6a(fmaxf(fmaf(-2.f, acc[mi][ni][3], x2v[mi][1] + m21), 0.f), ql[mi][1]);
                        acc[mi][ni][0] = 0.f; acc[mi][ni][1] = 0.f;
                        acc[mi][ni][2] = 0.f; acc[mi][ni][3] = 0.f;
                    }
            }
        }
    }

    // ---- quad merge (same 4 rows within a quad), snapshot-before-insert
#pragma unroll
    for (int off = 2; off > 0; off >>= 1) {
#pragma unroll
        for (int mi = 0; mi < 2; mi++)
#pragma unroll
            for (int p = 0; p < 2; p++) {
                float t[6];
#pragma unroll
                for (int j = 0; j < 6; j++)
                    t[j] = __shfl_down_sync(0xffffffffu, ql[mi][p][j], off, 4);
#pragma unroll
                for (int j = 0; j < 6; j++) insert6a(t[j], ql[mi][p]);
            }
    }

    // ---- cross merge staging: 4 lists/row = quarter, 6 values each
    if (qd == 0) {
#pragma unroll
        for (int mi = 0; mi < 2; mi++)
#pragma unroll
            for (int p = 0; p < 2; p++) {
                int r = wm * 32 + mi * 16 + g + p * 8;
#pragma unroll
                for (int j = 0; j < 6; j++)
                    stage[r * 24 + qtr * 6 + j] = ql[mi][p][j];
            }
    }
    __syncthreads();

    float part = 0.f;
    if (tid < 128) {
        float f[6] = {INFINITY, INFINITY, INFINITY, INFINITY, INFINITY, INFINITY};
        const float* sr = stage + tid * 24;
#pragma unroll
        for (int i = 0; i < 24; i++) insert6a(sr[i], f);
        float rv = rptr[0];
        float r2 = rv * rv;
        part = fmaxf(f[0] - r2, 0.f) + fmaxf(f[1] - r2, 0.f) + fmaxf(f[2] - r2, 0.f)
             + fmaxf(r2 - f[3] - ALPHA_C, 0.f) + fmaxf(r2 - f[4] - ALPHA_C, 0.f)
             + fmaxf(r2 - f[5] - ALPHA_C, 0.f);
    }
    __syncthreads();
    float* red = stage;
    red[tid] = part;
    __syncthreads();
#pragma unroll
    for (int o = 256; o > 0; o >>= 1) {
        if (tid < o) red[tid] += red[tid + o];
        __syncthreads();
    }
    if (tid == 0) g_part[blockIdx.x] = red[0];
}

// Deterministic final reduction
__global__ void finalize_loss(float* __restrict__ out) {
    __shared__ float s[128];
    int t = threadIdx.x;
    s[t] = g_part[t];
    __syncthreads();
#pragma unroll
    for (int o = 64; o > 0; o >>= 1) {
        if (t < o) s[t] += s[t + o];
        __syncthreads();
    }
    if (t == 0) out[0] = s[0] * (1.0f / (49152.0f * NU_C));
}

// ---------------- launch ----------------
extern "C" void kernel_launch(void* const* d_in, const int* in_sizes, int n_in,
                              void* d_out, int out_size) {
    (void)in_sizes; (void)n_in; (void)out_size;
    const float* phi = (const float*)d_in[0];
    const float* mem = (const float*)d_in[1];
    const float* r   = (const float*)d_in[2];
    float* out = (float*)d_out;

    cudaFuncSetAttribute(knn_gemm, cudaFuncAttributeMaxDynamicSharedMemorySize, SMEM_BYTES);

    prep_phi_x2<<<dim3(128, 4), dim3(32, 8)>>>(phi);
    prep_mem<<<NDIM / 8, 256>>>(mem);
    knn_gemm<<<MDIM / MT, 512, SMEM_BYTES>>>(r);
    finalize_loss<<<1, 128>>>(out);
}